// round 1
// baseline (speedup 1.0000x reference)
#include <cuda_runtime.h>
#include <math.h>

#define D_MODEL 1024
#define D_FF    4096
#define BATCH   4
#define SEQ     2048
#define NTOK    (BATCH * SEQ)   // 8192

// ---------------- scratch (allocation-free: __device__ globals) ----------------
__device__ float g_norm1[(size_t)NTOK * D_MODEL];   //  33.5 MB
__device__ float g_scores[(size_t)BATCH * SEQ * SEQ]; // 67 MB
__device__ float g_attn[(size_t)NTOK * D_MODEL];    //  33.5 MB
__device__ float g_x[(size_t)NTOK * D_MODEL];       //  33.5 MB
__device__ float g_norm2[(size_t)NTOK * D_MODEL];   //  33.5 MB
__device__ float g_h[(size_t)NTOK * D_FF];          // 134 MB

// ---------------- reductions ----------------
__device__ __forceinline__ float block_sum(float v, float* sh) {
    int lane = threadIdx.x & 31, w = threadIdx.x >> 5;
    #pragma unroll
    for (int o = 16; o; o >>= 1) v += __shfl_down_sync(0xffffffffu, v, o);
    if (lane == 0) sh[w] = v;
    __syncthreads();
    if (w == 0) {
        float t = (lane < 8) ? sh[lane] : 0.f;
        #pragma unroll
        for (int o = 4; o; o >>= 1) t += __shfl_down_sync(0xffffffffu, t, o);
        if (lane == 0) sh[0] = t;
    }
    __syncthreads();
    float r = sh[0];
    __syncthreads();
    return r;
}

__device__ __forceinline__ float block_max(float v, float* sh) {
    int lane = threadIdx.x & 31, w = threadIdx.x >> 5;
    #pragma unroll
    for (int o = 16; o; o >>= 1) v = fmaxf(v, __shfl_down_sync(0xffffffffu, v, o));
    if (lane == 0) sh[w] = v;
    __syncthreads();
    if (w == 0) {
        float t = (lane < 8) ? sh[lane] : -3.4e38f;
        #pragma unroll
        for (int o = 4; o; o >>= 1) t = fmaxf(t, __shfl_down_sync(0xffffffffu, t, o));
        if (lane == 0) sh[0] = t;
    }
    __syncthreads();
    float r = sh[0];
    __syncthreads();
    return r;
}

// ---------------- LayerNorm: one block per row of 1024 ----------------
__global__ __launch_bounds__(256) void ln_kernel(
    const float* __restrict__ in, const float* __restrict__ gamma,
    const float* __restrict__ beta, float* __restrict__ out)
{
    __shared__ float sh[32];
    size_t row = blockIdx.x;
    const float* x = in + row * D_MODEL;
    float v[4], s = 0.f;
    #pragma unroll
    for (int i = 0; i < 4; i++) { v[i] = x[threadIdx.x + i * 256]; s += v[i]; }
    float mean = block_sum(s, sh) * (1.0f / D_MODEL);
    float q = 0.f;
    #pragma unroll
    for (int i = 0; i < 4; i++) { float d = v[i] - mean; q += d * d; }
    float var = block_sum(q, sh) * (1.0f / D_MODEL);
    float rstd = rsqrtf(var + 1e-5f);
    float* y = out + row * D_MODEL;
    #pragma unroll
    for (int i = 0; i < 4; i++) {
        int c = threadIdx.x + i * 256;
        y[c] = (v[i] - mean) * rstd * gamma[c] + beta[c];
    }
}

// ---------------- fused residual add + LayerNorm ----------------
__global__ __launch_bounds__(256) void add_ln_kernel(
    const float* __restrict__ src, const float* __restrict__ attn,
    const float* __restrict__ gamma, const float* __restrict__ beta,
    float* __restrict__ xout, float* __restrict__ nout)
{
    __shared__ float sh[32];
    size_t row = blockIdx.x;
    const float* a = src + row * D_MODEL;
    const float* b = attn + row * D_MODEL;
    float v[4], s = 0.f;
    #pragma unroll
    for (int i = 0; i < 4; i++) {
        int c = threadIdx.x + i * 256;
        v[i] = a[c] + b[c];
        s += v[i];
    }
    float* xo = xout + row * D_MODEL;
    #pragma unroll
    for (int i = 0; i < 4; i++) xo[threadIdx.x + i * 256] = v[i];
    float mean = block_sum(s, sh) * (1.0f / D_MODEL);
    float q = 0.f;
    #pragma unroll
    for (int i = 0; i < 4; i++) { float d = v[i] - mean; q += d * d; }
    float var = block_sum(q, sh) * (1.0f / D_MODEL);
    float rstd = rsqrtf(var + 1e-5f);
    float* y = nout + row * D_MODEL;
    #pragma unroll
    for (int i = 0; i < 4; i++) {
        int c = threadIdx.x + i * 256;
        y[c] = (v[i] - mean) * rstd * gamma[c] + beta[c];
    }
}

// ---------------- softmax over rows of length SEQ (in place) ----------------
__global__ __launch_bounds__(256) void softmax_kernel(float* __restrict__ sc)
{
    __shared__ float sh[32];
    size_t row = blockIdx.x;
    float* p = sc + row * (size_t)SEQ;
    float v[8], m = -3.4e38f;
    #pragma unroll
    for (int i = 0; i < 8; i++) { v[i] = p[threadIdx.x + i * 256]; m = fmaxf(m, v[i]); }
    m = block_max(m, sh);
    float s = 0.f;
    #pragma unroll
    for (int i = 0; i < 8; i++) { v[i] = expf(v[i] - m); s += v[i]; }
    s = block_sum(s, sh);
    float inv = 1.0f / s;
    #pragma unroll
    for (int i = 0; i < 8; i++) p[threadIdx.x + i * 256] = v[i] * inv;
}

// ---------------- tiled SGEMM (128x128x8, 256 threads, 8x8 microtile) ----------
// epi: 0 = C = scale*AB
//      1 = C = gelu(AB + bias[col])
//      2 = C = AB + bias[col] + resid[row,col]
#define BM 128
#define BN 128
#define BK 8
#define TM 8
#define TN 8

__device__ __forceinline__ float gelu_exact(float v) {
    return v * 0.5f * (1.0f + erff(v * 0.70710678118654752f));
}

// NN: C[M,N] = A[M,K] * B[K,N]
__global__ __launch_bounds__(256) void sgemm_nn(
    const float* __restrict__ A, const float* __restrict__ B, float* __restrict__ C,
    int M, int N, int K, size_t sA, size_t sB, size_t sC,
    const float* __restrict__ bias, const float* __restrict__ resid,
    float scale, int epi)
{
    A += blockIdx.z * sA; B += blockIdx.z * sB; C += blockIdx.z * sC;
    if (resid) resid += blockIdx.z * sC;
    __shared__ float As[BK][BM];
    __shared__ float Bs[BK][BN];
    int tid = threadIdx.x;
    int tx = tid & 15;      // N dir
    int ty = tid >> 4;      // M dir
    int arow = tid >> 1;           // 0..127
    int acol = (tid & 1) * 4;      // 0 or 4
    int brow = tid >> 5;           // 0..7
    int bcol = (tid & 31) * 4;
    const float* Aptr = A + (size_t)(blockIdx.y * BM + arow) * K + acol;
    const float* Bptr = B + (size_t)brow * N + blockIdx.x * BN + bcol;
    float acc[TM][TN] = {};
    for (int k0 = 0; k0 < K; k0 += BK) {
        float4 a4 = *(const float4*)Aptr;
        float4 b4 = *(const float4*)Bptr;
        As[acol + 0][arow] = a4.x;
        As[acol + 1][arow] = a4.y;
        As[acol + 2][arow] = a4.z;
        As[acol + 3][arow] = a4.w;
        *(float4*)&Bs[brow][bcol] = b4;
        __syncthreads();
        #pragma unroll
        for (int k = 0; k < BK; k++) {
            float ar[TM], br[TN];
            #pragma unroll
            for (int i = 0; i < TM; i++) ar[i] = As[k][ty * TM + i];
            #pragma unroll
            for (int j = 0; j < TN; j++) br[j] = Bs[k][tx * TN + j];
            #pragma unroll
            for (int i = 0; i < TM; i++)
                #pragma unroll
                for (int j = 0; j < TN; j++) acc[i][j] = fmaf(ar[i], br[j], acc[i][j]);
        }
        __syncthreads();
        Aptr += BK;
        Bptr += (size_t)BK * N;
    }
    int r0 = blockIdx.y * BM + ty * TM;
    int c0 = blockIdx.x * BN + tx * TN;
    #pragma unroll
    for (int i = 0; i < TM; i++) {
        size_t base = (size_t)(r0 + i) * N + c0;
        #pragma unroll
        for (int j = 0; j < TN; j++) {
            float v = acc[i][j];
            if (epi == 0) v *= scale;
            else if (epi == 1) v = gelu_exact(v + bias[c0 + j]);
            else v = v + bias[c0 + j] + resid[base + j];
            C[base + j] = v;
        }
    }
}

// NT: C[M,N] = A[M,K] * B[N,K]^T   (both operands K-contiguous)
__global__ __launch_bounds__(256) void sgemm_nt(
    const float* __restrict__ A, const float* __restrict__ B, float* __restrict__ C,
    int M, int N, int K, size_t sA, size_t sB, size_t sC, float scale)
{
    A += blockIdx.z * sA; B += blockIdx.z * sB; C += blockIdx.z * sC;
    __shared__ float As[BK][BM];
    __shared__ float Bs[BK][BN];
    int tid = threadIdx.x;
    int tx = tid & 15;
    int ty = tid >> 4;
    int lrow = tid >> 1;
    int lcol = (tid & 1) * 4;
    const float* Aptr = A + (size_t)(blockIdx.y * BM + lrow) * K + lcol;
    const float* Bptr = B + (size_t)(blockIdx.x * BN + lrow) * K + lcol;
    float acc[TM][TN] = {};
    for (int k0 = 0; k0 < K; k0 += BK) {
        float4 a4 = *(const float4*)Aptr;
        float4 b4 = *(const float4*)Bptr;
        As[lcol + 0][lrow] = a4.x;
        As[lcol + 1][lrow] = a4.y;
        As[lcol + 2][lrow] = a4.z;
        As[lcol + 3][lrow] = a4.w;
        Bs[lcol + 0][lrow] = b4.x;
        Bs[lcol + 1][lrow] = b4.y;
        Bs[lcol + 2][lrow] = b4.z;
        Bs[lcol + 3][lrow] = b4.w;
        __syncthreads();
        #pragma unroll
        for (int k = 0; k < BK; k++) {
            float ar[TM], br[TN];
            #pragma unroll
            for (int i = 0; i < TM; i++) ar[i] = As[k][ty * TM + i];
            #pragma unroll
            for (int j = 0; j < TN; j++) br[j] = Bs[k][tx * TN + j];
            #pragma unroll
            for (int i = 0; i < TM; i++)
                #pragma unroll
                for (int j = 0; j < TN; j++) acc[i][j] = fmaf(ar[i], br[j], acc[i][j]);
        }
        __syncthreads();
        Aptr += BK;
        Bptr += BK;
    }
    int r0 = blockIdx.y * BM + ty * TM;
    int c0 = blockIdx.x * BN + tx * TN;
    #pragma unroll
    for (int i = 0; i < TM; i++) {
        size_t base = (size_t)(r0 + i) * N + c0;
        #pragma unroll
        for (int j = 0; j < TN; j++) C[base + j] = acc[i][j] * scale;
    }
}

// ---------------- launch ----------------
extern "C" void kernel_launch(void* const* d_in, const int* in_sizes, int n_in,
                              void* d_out, int out_size)
{
    const float* src    = (const float*)d_in[0];
    const float* gamma1 = (const float*)d_in[1];
    const float* beta1  = (const float*)d_in[2];
    const float* gamma2 = (const float*)d_in[3];
    const float* beta2  = (const float*)d_in[4];
    const float* w1     = (const float*)d_in[5];
    const float* b1     = (const float*)d_in[6];
    const float* w2     = (const float*)d_in[7];
    const float* b2     = (const float*)d_in[8];
    float* out = (float*)d_out;

    float *norm1, *scores, *attn, *x, *norm2, *h;
    cudaGetSymbolAddress((void**)&norm1, g_norm1);
    cudaGetSymbolAddress((void**)&scores, g_scores);
    cudaGetSymbolAddress((void**)&attn, g_attn);
    cudaGetSymbolAddress((void**)&x, g_x);
    cudaGetSymbolAddress((void**)&norm2, g_norm2);
    cudaGetSymbolAddress((void**)&h, g_h);

    const size_t SD = (size_t)SEQ * D_MODEL;   // per-batch stride of [S, D]
    const size_t SS = (size_t)SEQ * SEQ;       // per-batch stride of [S, S]

    // 1. norm1 = LN(src)
    ln_kernel<<<NTOK, 256>>>(src, gamma1, beta1, norm1);

    // 2. scores[b] = norm1[b] @ norm1[b]^T / 32
    sgemm_nt<<<dim3(SEQ / BN, SEQ / BM, BATCH), 256>>>(
        norm1, norm1, scores, SEQ, SEQ, D_MODEL, SD, SD, SS, 0.03125f);

    // 3. softmax rows
    softmax_kernel<<<BATCH * SEQ, 256>>>(scores);

    // 4. attn[b] = scores[b] @ norm1[b]
    sgemm_nn<<<dim3(D_MODEL / BN, SEQ / BM, BATCH), 256>>>(
        scores, norm1, attn, SEQ, D_MODEL, SEQ, SS, SD, SD,
        nullptr, nullptr, 1.0f, 0);

    // 5. x = src + attn ; norm2 = LN(x)
    add_ln_kernel<<<NTOK, 256>>>(src, attn, gamma2, beta2, x, norm2);

    // 6. h = gelu(norm2 @ w1 + b1)
    sgemm_nn<<<dim3(D_FF / BN, NTOK / BM, 1), 256>>>(
        norm2, w1, h, NTOK, D_FF, D_MODEL, 0, 0, 0, b1, nullptr, 1.0f, 1);

    // 7. out = h @ w2 + b2 + x
    sgemm_nn<<<dim3(D_MODEL / BN, NTOK / BM, 1), 256>>>(
        h, w2, out, NTOK, D_MODEL, D_FF, 0, 0, 0, b2, x, 1.0f, 2);

    (void)in_sizes; (void)n_in; (void)out_size;
}

// round 2
// speedup vs baseline: 2.1585x; 2.1585x over previous
#include <cuda_runtime.h>
#include <math.h>
#include <stdint.h>

#define D_MODEL 1024
#define D_FF    4096
#define BATCH   4
#define SEQ     2048
#define NTOK    (BATCH * SEQ)   // 8192

// ---------------- scratch (allocation-free: __device__ globals) ----------------
__device__ float g_norm1[(size_t)NTOK * D_MODEL];
__device__ float g_scores[(size_t)BATCH * SEQ * SEQ];
__device__ float g_attn[(size_t)NTOK * D_MODEL];
__device__ float g_x[(size_t)NTOK * D_MODEL];
__device__ float g_norm2[(size_t)NTOK * D_MODEL];
__device__ float g_h[(size_t)NTOK * D_FF];

// ---------------- reductions ----------------
__device__ __forceinline__ float block_sum(float v, float* sh) {
    int lane = threadIdx.x & 31, w = threadIdx.x >> 5;
    #pragma unroll
    for (int o = 16; o; o >>= 1) v += __shfl_down_sync(0xffffffffu, v, o);
    if (lane == 0) sh[w] = v;
    __syncthreads();
    if (w == 0) {
        float t = (lane < 8) ? sh[lane] : 0.f;
        #pragma unroll
        for (int o = 4; o; o >>= 1) t += __shfl_down_sync(0xffffffffu, t, o);
        if (lane == 0) sh[0] = t;
    }
    __syncthreads();
    float r = sh[0];
    __syncthreads();
    return r;
}

__device__ __forceinline__ float block_max(float v, float* sh) {
    int lane = threadIdx.x & 31, w = threadIdx.x >> 5;
    #pragma unroll
    for (int o = 16; o; o >>= 1) v = fmaxf(v, __shfl_down_sync(0xffffffffu, v, o));
    if (lane == 0) sh[w] = v;
    __syncthreads();
    if (w == 0) {
        float t = (lane < 8) ? sh[lane] : -3.4e38f;
        #pragma unroll
        for (int o = 4; o; o >>= 1) t = fmaxf(t, __shfl_down_sync(0xffffffffu, t, o));
        if (lane == 0) sh[0] = t;
    }
    __syncthreads();
    float r = sh[0];
    __syncthreads();
    return r;
}

// ---------------- LayerNorm: one block per row of 1024 ----------------
__global__ __launch_bounds__(256) void ln_kernel(
    const float* __restrict__ in, const float* __restrict__ gamma,
    const float* __restrict__ beta, float* __restrict__ out)
{
    __shared__ float sh[32];
    size_t row = blockIdx.x;
    const float* x = in + row * D_MODEL;
    float v[4], s = 0.f;
    #pragma unroll
    for (int i = 0; i < 4; i++) { v[i] = x[threadIdx.x + i * 256]; s += v[i]; }
    float mean = block_sum(s, sh) * (1.0f / D_MODEL);
    float q = 0.f;
    #pragma unroll
    for (int i = 0; i < 4; i++) { float d = v[i] - mean; q += d * d; }
    float var = block_sum(q, sh) * (1.0f / D_MODEL);
    float rstd = rsqrtf(var + 1e-5f);
    float* y = out + row * D_MODEL;
    #pragma unroll
    for (int i = 0; i < 4; i++) {
        int c = threadIdx.x + i * 256;
        y[c] = (v[i] - mean) * rstd * gamma[c] + beta[c];
    }
}

// ---------------- fused residual add + LayerNorm ----------------
__global__ __launch_bounds__(256) void add_ln_kernel(
    const float* __restrict__ src, const float* __restrict__ attn,
    const float* __restrict__ gamma, const float* __restrict__ beta,
    float* __restrict__ xout, float* __restrict__ nout)
{
    __shared__ float sh[32];
    size_t row = blockIdx.x;
    const float* a = src + row * D_MODEL;
    const float* b = attn + row * D_MODEL;
    float v[4], s = 0.f;
    #pragma unroll
    for (int i = 0; i < 4; i++) {
        int c = threadIdx.x + i * 256;
        v[i] = a[c] + b[c];
        s += v[i];
    }
    float* xo = xout + row * D_MODEL;
    #pragma unroll
    for (int i = 0; i < 4; i++) xo[threadIdx.x + i * 256] = v[i];
    float mean = block_sum(s, sh) * (1.0f / D_MODEL);
    float q = 0.f;
    #pragma unroll
    for (int i = 0; i < 4; i++) { float d = v[i] - mean; q += d * d; }
    float var = block_sum(q, sh) * (1.0f / D_MODEL);
    float rstd = rsqrtf(var + 1e-5f);
    float* y = nout + row * D_MODEL;
    #pragma unroll
    for (int i = 0; i < 4; i++) {
        int c = threadIdx.x + i * 256;
        y[c] = (v[i] - mean) * rstd * gamma[c] + beta[c];
    }
}

// ---------------- softmax over rows of length SEQ (in place) ----------------
__global__ __launch_bounds__(256) void softmax_kernel(float* __restrict__ sc)
{
    __shared__ float sh[32];
    size_t row = blockIdx.x;
    float* p = sc + row * (size_t)SEQ;
    float v[8], m = -3.4e38f;
    #pragma unroll
    for (int i = 0; i < 8; i++) { v[i] = p[threadIdx.x + i * 256]; m = fmaxf(m, v[i]); }
    m = block_max(m, sh);
    float s = 0.f;
    #pragma unroll
    for (int i = 0; i < 8; i++) { v[i] = expf(v[i] - m); s += v[i]; }
    s = block_sum(s, sh);
    float inv = 1.0f / s;
    #pragma unroll
    for (int i = 0; i < 8; i++) p[threadIdx.x + i * 256] = v[i] * inv;
}

// ======================= TF32 tensor-core GEMM ============================
// Block tile 128x128, BK=16, 256 threads = 8 warps (2 in M x 4 in N),
// warp tile 64x32 via mma.sync.m16n8k8.tf32. Double-buffered smem, row
// stride 136 (== 8 mod 32) -> conflict-free STS-transpose and LDS fragments.
// EPI: 0 = scale*AB   1 = gelu(AB + bias)   2 = AB + bias + resid

__device__ __forceinline__ uint32_t f2tf32(float x) {
    uint32_t u;
    asm("cvt.rna.tf32.f32 %0, %1;" : "=r"(u) : "f"(x));
    return u;
}

__device__ __forceinline__ void mma8(float* c, const uint32_t* a, const uint32_t* b) {
    asm volatile(
        "mma.sync.aligned.m16n8k8.row.col.f32.tf32.tf32.f32 "
        "{%0,%1,%2,%3}, {%4,%5,%6,%7}, {%8,%9}, {%0,%1,%2,%3};"
        : "+f"(c[0]), "+f"(c[1]), "+f"(c[2]), "+f"(c[3])
        : "r"(a[0]), "r"(a[1]), "r"(a[2]), "r"(a[3]), "r"(b[0]), "r"(b[1]));
}

__device__ __forceinline__ float gelu_exact(float v) {
    return v * 0.5f * (1.0f + erff(v * 0.70710678118654752f));
}

#define SMS 136   // smem row stride (floats)

template<int TRANS_B, int EPI>
__global__ __launch_bounds__(256) void gemm_tf32(
    const float* __restrict__ A, const float* __restrict__ B, float* __restrict__ C,
    int M, int N, int K, size_t sA, size_t sB, size_t sC,
    const float* __restrict__ bias, const float* __restrict__ resid, float scale)
{
    A += blockIdx.z * sA; B += blockIdx.z * sB; C += blockIdx.z * sC;
    if (EPI == 2) resid += blockIdx.z * sC;

    __shared__ uint32_t As[2][16][SMS];
    __shared__ uint32_t Bs[2][16][SMS];

    const int tid  = threadIdx.x;
    const int lane = tid & 31;
    const int warp = tid >> 5;
    const int warpM = warp >> 2;   // 0..1
    const int warpN = warp & 3;    // 0..3
    const int r  = lane >> 2;      // groupID 0..7
    const int cq = lane & 3;       // threadID_in_group 0..3

    const int row0 = blockIdx.y * 128;
    const int col0 = blockIdx.x * 128;

    // ---- global load indexing ----
    const int am  = tid & 127;     // m within tile
    const int akg = tid >> 7;      // 0..1 : k-group (cols akg*4.. and akg*4+8..)
    const float* pA = A + (size_t)(row0 + am) * K + akg * 4;

    const float* pB;
    int bn4 = 0, bkq = 0;
    if (TRANS_B) {
        pB = B + (size_t)(col0 + am) * K + akg * 4;   // same pattern as A
    } else {
        bn4 = (tid & 31) * 4;   // n offset
        bkq = tid >> 5;         // 0..7 : k row (and +8)
        pB = B + (size_t)bkq * N + col0 + bn4;
    }

    float acc[4][4][4] = {};
    float4 fa0, fa1, fb0, fb1;

    // ---- initial tile load ----
    fa0 = *(const float4*)(pA);
    fa1 = *(const float4*)(pA + 8);
    if (TRANS_B) {
        fb0 = *(const float4*)(pB);
        fb1 = *(const float4*)(pB + 8);
    } else {
        fb0 = *(const float4*)(pB);
        fb1 = *(const float4*)(pB + (size_t)8 * N);
    }

    // store tile -> smem buffer nb
    auto sts_tile = [&](int nb) {
        float a0[4] = {fa0.x, fa0.y, fa0.z, fa0.w};
        float a1[4] = {fa1.x, fa1.y, fa1.z, fa1.w};
        #pragma unroll
        for (int l = 0; l < 4; l++) {
            As[nb][akg * 4 + l][am]     = f2tf32(a0[l]);
            As[nb][akg * 4 + 8 + l][am] = f2tf32(a1[l]);
        }
        float b0[4] = {fb0.x, fb0.y, fb0.z, fb0.w};
        float b1[4] = {fb1.x, fb1.y, fb1.z, fb1.w};
        if (TRANS_B) {
            #pragma unroll
            for (int l = 0; l < 4; l++) {
                Bs[nb][akg * 4 + l][am]     = f2tf32(b0[l]);
                Bs[nb][akg * 4 + 8 + l][am] = f2tf32(b1[l]);
            }
        } else {
            #pragma unroll
            for (int l = 0; l < 4; l++) {
                Bs[nb][bkq][bn4 + l]     = f2tf32(b0[l]);
                Bs[nb][bkq + 8][bn4 + l] = f2tf32(b1[l]);
            }
        }
    };

    sts_tile(0);
    __syncthreads();

    int buf = 0;
    for (int k0 = 0; k0 < K; k0 += 16) {
        const bool more = (k0 + 16 < K);
        if (more) {
            // prefetch next tile into registers (latency overlapped by compute)
            fa0 = *(const float4*)(pA + k0 + 16);
            fa1 = *(const float4*)(pA + k0 + 24);
            if (TRANS_B) {
                fb0 = *(const float4*)(pB + k0 + 16);
                fb1 = *(const float4*)(pB + k0 + 24);
            } else {
                fb0 = *(const float4*)(pB + (size_t)(k0 + 16) * N);
                fb1 = *(const float4*)(pB + (size_t)(k0 + 24) * N);
            }
        }

        // ---- compute over current buffer ----
        #pragma unroll
        for (int ks = 0; ks < 16; ks += 8) {
            uint32_t afr[4][4], bfr[4][2];
            #pragma unroll
            for (int i = 0; i < 4; i++) {
                int m = warpM * 64 + i * 16 + r;
                afr[i][0] = As[buf][ks + cq][m];
                afr[i][1] = As[buf][ks + cq][m + 8];
                afr[i][2] = As[buf][ks + cq + 4][m];
                afr[i][3] = As[buf][ks + cq + 4][m + 8];
            }
            #pragma unroll
            for (int j = 0; j < 4; j++) {
                int n = warpN * 32 + j * 8 + r;
                bfr[j][0] = Bs[buf][ks + cq][n];
                bfr[j][1] = Bs[buf][ks + cq + 4][n];
            }
            #pragma unroll
            for (int i = 0; i < 4; i++)
                #pragma unroll
                for (int j = 0; j < 4; j++)
                    mma8(acc[i][j], afr[i], bfr[j]);
        }

        if (more) {
            sts_tile(buf ^ 1);
            __syncthreads();
            buf ^= 1;
        }
    }

    // ---- epilogue ----
    #pragma unroll
    for (int i = 0; i < 4; i++) {
        int mrow = row0 + warpM * 64 + i * 16 + r;
        #pragma unroll
        for (int j = 0; j < 4; j++) {
            int ncol = col0 + warpN * 32 + j * 8 + 2 * cq;
            float v0 = acc[i][j][0], v1 = acc[i][j][1];
            float v2 = acc[i][j][2], v3 = acc[i][j][3];
            if (EPI == 0) {
                v0 *= scale; v1 *= scale; v2 *= scale; v3 *= scale;
            } else {
                float bb0 = bias[ncol], bb1 = bias[ncol + 1];
                if (EPI == 1) {
                    v0 = gelu_exact(v0 + bb0); v1 = gelu_exact(v1 + bb1);
                    v2 = gelu_exact(v2 + bb0); v3 = gelu_exact(v3 + bb1);
                } else {
                    size_t p0 = (size_t)mrow * N + ncol;
                    size_t p1 = (size_t)(mrow + 8) * N + ncol;
                    v0 += bb0 + resid[p0];     v1 += bb1 + resid[p0 + 1];
                    v2 += bb0 + resid[p1];     v3 += bb1 + resid[p1 + 1];
                }
            }
            size_t p0 = (size_t)mrow * N + ncol;
            size_t p1 = (size_t)(mrow + 8) * N + ncol;
            C[p0] = v0; C[p0 + 1] = v1;
            C[p1] = v2; C[p1 + 1] = v3;
        }
    }
}

// ---------------- launch ----------------
extern "C" void kernel_launch(void* const* d_in, const int* in_sizes, int n_in,
                              void* d_out, int out_size)
{
    const float* src    = (const float*)d_in[0];
    const float* gamma1 = (const float*)d_in[1];
    const float* beta1  = (const float*)d_in[2];
    const float* gamma2 = (const float*)d_in[3];
    const float* beta2  = (const float*)d_in[4];
    const float* w1     = (const float*)d_in[5];
    const float* b1     = (const float*)d_in[6];
    const float* w2     = (const float*)d_in[7];
    const float* b2     = (const float*)d_in[8];
    float* out = (float*)d_out;

    float *norm1, *scores, *attn, *x, *norm2, *h;
    cudaGetSymbolAddress((void**)&norm1, g_norm1);
    cudaGetSymbolAddress((void**)&scores, g_scores);
    cudaGetSymbolAddress((void**)&attn, g_attn);
    cudaGetSymbolAddress((void**)&x, g_x);
    cudaGetSymbolAddress((void**)&norm2, g_norm2);
    cudaGetSymbolAddress((void**)&h, g_h);

    const size_t SD = (size_t)SEQ * D_MODEL;
    const size_t SS = (size_t)SEQ * SEQ;

    // 1. norm1 = LN(src)
    ln_kernel<<<NTOK, 256>>>(src, gamma1, beta1, norm1);

    // 2. scores[b] = norm1[b] @ norm1[b]^T / 32
    gemm_tf32<1, 0><<<dim3(SEQ / 128, SEQ / 128, BATCH), 256>>>(
        norm1, norm1, scores, SEQ, SEQ, D_MODEL, SD, SD, SS,
        nullptr, nullptr, 0.03125f);

    // 3. softmax rows
    softmax_kernel<<<BATCH * SEQ, 256>>>(scores);

    // 4. attn[b] = scores[b] @ norm1[b]
    gemm_tf32<0, 0><<<dim3(D_MODEL / 128, SEQ / 128, BATCH), 256>>>(
        scores, norm1, attn, SEQ, D_MODEL, SEQ, SS, SD, SD,
        nullptr, nullptr, 1.0f);

    // 5. x = src + attn ; norm2 = LN(x)
    add_ln_kernel<<<NTOK, 256>>>(src, attn, gamma2, beta2, x, norm2);

    // 6. h = gelu(norm2 @ w1 + b1)
    gemm_tf32<0, 1><<<dim3(D_FF / 128, NTOK / 128, 1), 256>>>(
        norm2, w1, h, NTOK, D_FF, D_MODEL, 0, 0, 0, b1, nullptr, 1.0f);

    // 7. out = h @ w2 + b2 + x
    gemm_tf32<0, 2><<<dim3(D_MODEL / 128, NTOK / 128, 1), 256>>>(
        h, w2, out, NTOK, D_MODEL, D_FF, 0, 0, 0, b2, x, 1.0f);

    (void)in_sizes; (void)n_in; (void)out_size;
}

// round 3
// speedup vs baseline: 2.5264x; 1.1704x over previous
#include <cuda_runtime.h>
#include <math.h>
#include <stdint.h>

#define D_MODEL 1024
#define D_FF    4096
#define BATCH   4
#define SEQ     2048
#define NTOK    (BATCH * SEQ)   // 8192

// ---------------- scratch (allocation-free: __device__ globals) ----------------
__device__ float g_norm1[(size_t)NTOK * D_MODEL];
__device__ float g_scores[(size_t)BATCH * SEQ * SEQ];
__device__ float g_attn[(size_t)NTOK * D_MODEL];
__device__ float g_x[(size_t)NTOK * D_MODEL];
__device__ float g_norm2[(size_t)NTOK * D_MODEL];
__device__ float g_h[(size_t)NTOK * D_FF];

// ---------------- reductions ----------------
__device__ __forceinline__ float block_sum(float v, float* sh) {
    int lane = threadIdx.x & 31, w = threadIdx.x >> 5;
    #pragma unroll
    for (int o = 16; o; o >>= 1) v += __shfl_down_sync(0xffffffffu, v, o);
    if (lane == 0) sh[w] = v;
    __syncthreads();
    if (w == 0) {
        float t = (lane < 8) ? sh[lane] : 0.f;
        #pragma unroll
        for (int o = 4; o; o >>= 1) t += __shfl_down_sync(0xffffffffu, t, o);
        if (lane == 0) sh[0] = t;
    }
    __syncthreads();
    float r = sh[0];
    __syncthreads();
    return r;
}

__device__ __forceinline__ float block_max(float v, float* sh) {
    int lane = threadIdx.x & 31, w = threadIdx.x >> 5;
    #pragma unroll
    for (int o = 16; o; o >>= 1) v = fmaxf(v, __shfl_down_sync(0xffffffffu, v, o));
    if (lane == 0) sh[w] = v;
    __syncthreads();
    if (w == 0) {
        float t = (lane < 8) ? sh[lane] : -3.4e38f;
        #pragma unroll
        for (int o = 4; o; o >>= 1) t = fmaxf(t, __shfl_down_sync(0xffffffffu, t, o));
        if (lane == 0) sh[0] = t;
    }
    __syncthreads();
    float r = sh[0];
    __syncthreads();
    return r;
}

// ---------------- LayerNorm: one block per row of 1024 ----------------
__global__ __launch_bounds__(256) void ln_kernel(
    const float* __restrict__ in, const float* __restrict__ gamma,
    const float* __restrict__ beta, float* __restrict__ out)
{
    __shared__ float sh[32];
    size_t row = blockIdx.x;
    const float* x = in + row * D_MODEL;
    float v[4], s = 0.f;
    #pragma unroll
    for (int i = 0; i < 4; i++) { v[i] = x[threadIdx.x + i * 256]; s += v[i]; }
    float mean = block_sum(s, sh) * (1.0f / D_MODEL);
    float q = 0.f;
    #pragma unroll
    for (int i = 0; i < 4; i++) { float d = v[i] - mean; q += d * d; }
    float var = block_sum(q, sh) * (1.0f / D_MODEL);
    float rstd = rsqrtf(var + 1e-5f);
    float* y = out + row * D_MODEL;
    #pragma unroll
    for (int i = 0; i < 4; i++) {
        int c = threadIdx.x + i * 256;
        y[c] = (v[i] - mean) * rstd * gamma[c] + beta[c];
    }
}

// ---------------- fused residual add + LayerNorm ----------------
__global__ __launch_bounds__(256) void add_ln_kernel(
    const float* __restrict__ src, const float* __restrict__ attn,
    const float* __restrict__ gamma, const float* __restrict__ beta,
    float* __restrict__ xout, float* __restrict__ nout)
{
    __shared__ float sh[32];
    size_t row = blockIdx.x;
    const float* a = src + row * D_MODEL;
    const float* b = attn + row * D_MODEL;
    float v[4], s = 0.f;
    #pragma unroll
    for (int i = 0; i < 4; i++) {
        int c = threadIdx.x + i * 256;
        v[i] = a[c] + b[c];
        s += v[i];
    }
    float* xo = xout + row * D_MODEL;
    #pragma unroll
    for (int i = 0; i < 4; i++) xo[threadIdx.x + i * 256] = v[i];
    float mean = block_sum(s, sh) * (1.0f / D_MODEL);
    float q = 0.f;
    #pragma unroll
    for (int i = 0; i < 4; i++) { float d = v[i] - mean; q += d * d; }
    float var = block_sum(q, sh) * (1.0f / D_MODEL);
    float rstd = rsqrtf(var + 1e-5f);
    float* y = nout + row * D_MODEL;
    #pragma unroll
    for (int i = 0; i < 4; i++) {
        int c = threadIdx.x + i * 256;
        y[c] = (v[i] - mean) * rstd * gamma[c] + beta[c];
    }
}

// ---------------- softmax over rows of length SEQ (in place) ----------------
__global__ __launch_bounds__(256) void softmax_kernel(float* __restrict__ sc)
{
    __shared__ float sh[32];
    size_t row = blockIdx.x;
    float* p = sc + row * (size_t)SEQ;
    float v[8], m = -3.4e38f;
    #pragma unroll
    for (int i = 0; i < 8; i++) { v[i] = p[threadIdx.x + i * 256]; m = fmaxf(m, v[i]); }
    m = block_max(m, sh);
    float s = 0.f;
    #pragma unroll
    for (int i = 0; i < 8; i++) { v[i] = expf(v[i] - m); s += v[i]; }
    s = block_sum(s, sh);
    float inv = 1.0f / s;
    #pragma unroll
    for (int i = 0; i < 8; i++) p[threadIdx.x + i * 256] = v[i] * inv;
}

// ======================= TF32 tensor-core GEMM ============================
// Block tile 128x128, BK=8, 128 threads = 4 warps in 2x2, warp tile 64x64.
// mma.sync.m16n8k8.tf32. Double-buffered smem, row stride 136 -> conflict-free.
// EPI: 0 = scale*AB   1 = gelu(AB + bias)   2 = AB + bias + resid

__device__ __forceinline__ uint32_t f2tf32(float x) {
    uint32_t u;
    asm("cvt.rna.tf32.f32 %0, %1;" : "=r"(u) : "f"(x));
    return u;
}

__device__ __forceinline__ void mma8(float* c, const uint32_t* a, const uint32_t* b) {
    asm volatile(
        "mma.sync.aligned.m16n8k8.row.col.f32.tf32.tf32.f32 "
        "{%0,%1,%2,%3}, {%4,%5,%6,%7}, {%8,%9}, {%0,%1,%2,%3};"
        : "+f"(c[0]), "+f"(c[1]), "+f"(c[2]), "+f"(c[3])
        : "r"(a[0]), "r"(a[1]), "r"(a[2]), "r"(a[3]), "r"(b[0]), "r"(b[1]));
}

__device__ __forceinline__ float gelu_exact(float v) {
    return v * 0.5f * (1.0f + erff(v * 0.70710678118654752f));
}

#define SMS 136   // smem row stride (floats)

template<int TRANS_B, int EPI>
__global__ __launch_bounds__(128) void gemm_tf32(
    const float* __restrict__ A, const float* __restrict__ B, float* __restrict__ C,
    int M, int N, int K, size_t sA, size_t sB, size_t sC,
    const float* __restrict__ bias, const float* __restrict__ resid, float scale)
{
    A += blockIdx.z * sA; B += blockIdx.z * sB; C += blockIdx.z * sC;
    if (EPI == 2) resid += blockIdx.z * sC;

    __shared__ uint32_t As[2][8][SMS];
    __shared__ uint32_t Bs[2][8][SMS];

    const int tid  = threadIdx.x;
    const int lane = tid & 31;
    const int warp = tid >> 5;
    const int warpM = warp >> 1;   // 0..1
    const int warpN = warp & 1;    // 0..1
    const int r  = lane >> 2;      // 0..7
    const int cq = lane & 3;       // 0..3

    const int row0 = blockIdx.y * 128;
    const int col0 = blockIdx.x * 128;

    // ---- global load indexing ----
    const float* pA = A + (size_t)(row0 + tid) * K;      // 8 floats per k-tile

    const float* pB;
    int bkq = 0, bn = 0;
    if (TRANS_B) {
        pB = B + (size_t)(col0 + tid) * K;
    } else {
        bkq = tid >> 4;          // 0..7 : k row
        bn  = (tid & 15) * 4;    // n offset (plus +64 for second quad)
        pB = B + (size_t)bkq * N + col0 + bn;
    }

    float acc[4][8][4] = {};
    float4 fa0, fa1, fb0, fb1;

    auto ldg_tile = [&](int k0) {
        fa0 = *(const float4*)(pA + k0);
        fa1 = *(const float4*)(pA + k0 + 4);
        if (TRANS_B) {
            fb0 = *(const float4*)(pB + k0);
            fb1 = *(const float4*)(pB + k0 + 4);
        } else {
            fb0 = *(const float4*)(pB + (size_t)k0 * N);
            fb1 = *(const float4*)(pB + (size_t)k0 * N + 64);
        }
    };

    auto sts_tile = [&](int nb) {
        float a0[4] = {fa0.x, fa0.y, fa0.z, fa0.w};
        float a1[4] = {fa1.x, fa1.y, fa1.z, fa1.w};
        #pragma unroll
        for (int l = 0; l < 4; l++) {
            As[nb][l][tid]     = f2tf32(a0[l]);
            As[nb][4 + l][tid] = f2tf32(a1[l]);
        }
        float b0[4] = {fb0.x, fb0.y, fb0.z, fb0.w};
        float b1[4] = {fb1.x, fb1.y, fb1.z, fb1.w};
        if (TRANS_B) {
            #pragma unroll
            for (int l = 0; l < 4; l++) {
                Bs[nb][l][tid]     = f2tf32(b0[l]);
                Bs[nb][4 + l][tid] = f2tf32(b1[l]);
            }
        } else {
            uint4 u0, u1;
            u0.x = f2tf32(b0[0]); u0.y = f2tf32(b0[1]);
            u0.z = f2tf32(b0[2]); u0.w = f2tf32(b0[3]);
            u1.x = f2tf32(b1[0]); u1.y = f2tf32(b1[1]);
            u1.z = f2tf32(b1[2]); u1.w = f2tf32(b1[3]);
            *(uint4*)&Bs[nb][bkq][bn]      = u0;
            *(uint4*)&Bs[nb][bkq][bn + 64] = u1;
        }
    };

    ldg_tile(0);
    sts_tile(0);
    __syncthreads();

    int buf = 0;
    for (int k0 = 0; k0 < K; k0 += 8) {
        const bool more = (k0 + 8 < K);
        if (more) ldg_tile(k0 + 8);

        // ---- compute on current buffer ----
        uint32_t afr[4][4], bfr[8][2];
        #pragma unroll
        for (int i = 0; i < 4; i++) {
            int m = warpM * 64 + i * 16 + r;
            afr[i][0] = As[buf][cq][m];
            afr[i][1] = As[buf][cq][m + 8];
            afr[i][2] = As[buf][cq + 4][m];
            afr[i][3] = As[buf][cq + 4][m + 8];
        }
        #pragma unroll
        for (int j = 0; j < 8; j++) {
            int n = warpN * 64 + j * 8 + r;
            bfr[j][0] = Bs[buf][cq][n];
            bfr[j][1] = Bs[buf][cq + 4][n];
        }
        #pragma unroll
        for (int i = 0; i < 4; i++)
            #pragma unroll
            for (int j = 0; j < 8; j++)
                mma8(acc[i][j], afr[i], bfr[j]);

        if (more) {
            sts_tile(buf ^ 1);
            __syncthreads();
            buf ^= 1;
        }
    }

    // ---- epilogue ----
    #pragma unroll
    for (int i = 0; i < 4; i++) {
        int mrow = row0 + warpM * 64 + i * 16 + r;
        #pragma unroll
        for (int j = 0; j < 8; j++) {
            int ncol = col0 + warpN * 64 + j * 8 + 2 * cq;
            float v0 = acc[i][j][0], v1 = acc[i][j][1];
            float v2 = acc[i][j][2], v3 = acc[i][j][3];
            if (EPI == 0) {
                v0 *= scale; v1 *= scale; v2 *= scale; v3 *= scale;
            } else {
                float bb0 = bias[ncol], bb1 = bias[ncol + 1];
                if (EPI == 1) {
                    v0 = gelu_exact(v0 + bb0); v1 = gelu_exact(v1 + bb1);
                    v2 = gelu_exact(v2 + bb0); v3 = gelu_exact(v3 + bb1);
                } else {
                    size_t p0 = (size_t)mrow * N + ncol;
                    size_t p1 = (size_t)(mrow + 8) * N + ncol;
                    v0 += bb0 + resid[p0];     v1 += bb1 + resid[p0 + 1];
                    v2 += bb0 + resid[p1];     v3 += bb1 + resid[p1 + 1];
                }
            }
            size_t p0 = (size_t)mrow * N + ncol;
            size_t p1 = (size_t)(mrow + 8) * N + ncol;
            C[p0] = v0; C[p0 + 1] = v1;
            C[p1] = v2; C[p1 + 1] = v3;
        }
    }
}

// ---------------- launch ----------------
extern "C" void kernel_launch(void* const* d_in, const int* in_sizes, int n_in,
                              void* d_out, int out_size)
{
    const float* src    = (const float*)d_in[0];
    const float* gamma1 = (const float*)d_in[1];
    const float* beta1  = (const float*)d_in[2];
    const float* gamma2 = (const float*)d_in[3];
    const float* beta2  = (const float*)d_in[4];
    const float* w1     = (const float*)d_in[5];
    const float* b1     = (const float*)d_in[6];
    const float* w2     = (const float*)d_in[7];
    const float* b2     = (const float*)d_in[8];
    float* out = (float*)d_out;

    float *norm1, *scores, *attn, *x, *norm2, *h;
    cudaGetSymbolAddress((void**)&norm1, g_norm1);
    cudaGetSymbolAddress((void**)&scores, g_scores);
    cudaGetSymbolAddress((void**)&attn, g_attn);
    cudaGetSymbolAddress((void**)&x, g_x);
    cudaGetSymbolAddress((void**)&norm2, g_norm2);
    cudaGetSymbolAddress((void**)&h, g_h);

    const size_t SD = (size_t)SEQ * D_MODEL;
    const size_t SS = (size_t)SEQ * SEQ;

    // 1. norm1 = LN(src)
    ln_kernel<<<NTOK, 256>>>(src, gamma1, beta1, norm1);

    // 2. scores[b] = norm1[b] @ norm1[b]^T / 32
    gemm_tf32<1, 0><<<dim3(SEQ / 128, SEQ / 128, BATCH), 128>>>(
        norm1, norm1, scores, SEQ, SEQ, D_MODEL, SD, SD, SS,
        nullptr, nullptr, 0.03125f);

    // 3. softmax rows
    softmax_kernel<<<BATCH * SEQ, 256>>>(scores);

    // 4. attn[b] = scores[b] @ norm1[b]
    gemm_tf32<0, 0><<<dim3(D_MODEL / 128, SEQ / 128, BATCH), 128>>>(
        scores, norm1, attn, SEQ, D_MODEL, SEQ, SS, SD, SD,
        nullptr, nullptr, 1.0f);

    // 5. x = src + attn ; norm2 = LN(x)
    add_ln_kernel<<<NTOK, 256>>>(src, attn, gamma2, beta2, x, norm2);

    // 6. h = gelu(norm2 @ w1 + b1)
    gemm_tf32<0, 1><<<dim3(D_FF / 128, NTOK / 128, 1), 128>>>(
        norm2, w1, h, NTOK, D_FF, D_MODEL, 0, 0, 0, b1, nullptr, 1.0f);

    // 7. out = h @ w2 + b2 + x
    gemm_tf32<0, 2><<<dim3(D_MODEL / 128, NTOK / 128, 1), 128>>>(
        h, w2, out, NTOK, D_MODEL, D_FF, 0, 0, 0, b2, x, 1.0f);

    (void)in_sizes; (void)n_in; (void)out_size;
}